// round 8
// baseline (speedup 1.0000x reference)
#include <cuda_runtime.h>
#include <cstdint>
#include <cstddef>

#define BDIM 8192
#define CDIM 256
#define NITER 100
#define NCHUNK (BDIM * 8)     // 65536 chunk work-units per pass
#define NPASS (2 * NITER)
#define L2E 1.4426950408889634f
#define LN2 0.69314718055994531f

// Scratch: __device__ globals (no cudaMalloc allowed)
__device__ __align__(256) float g_M [(size_t)BDIM * BDIM];  // M[i][j]  = 2*x_i.y_j
__device__ __align__(256) float g_MT[(size_t)BDIM * BDIM];  // MT[j][i] = M[i][j]
__device__ __align__(256) float g_a[BDIM];
__device__ __align__(256) float g_b[BDIM];

// Work-stealing state. g_tickets zeroed each launch by init_b_kernel;
// g_rowcnt is self-resetting (finisher restores 0 for the next pass).
__device__ __align__(256) int    g_tickets[NPASS];
__device__ __align__(256) int    g_rowcnt[BDIM];
__device__ __align__(256) float2 g_pp[NCHUNK];      // per-chunk (max, sum)

__device__ __forceinline__ float ex2f(float x) {
    float y; asm("ex2.approx.f32 %0, %1;" : "=f"(y) : "f"(x)); return y;
}
__device__ __forceinline__ float lg2f(float x) {
    float y; asm("lg2.approx.f32 %0, %1;" : "=f"(y) : "f"(x)); return y;
}

// ---------------------------------------------------------------------------
// b init: b[j] = -||y_j||^2 (one warp per row). Also resets tickets/rowcnt.
// ---------------------------------------------------------------------------
__global__ __launch_bounds__(256) void init_b_kernel(const float* __restrict__ Y)
{
    if (blockIdx.x == 0 && threadIdx.x < NPASS) g_tickets[threadIdx.x] = 0;
    if (threadIdx.x < 8) g_rowcnt[blockIdx.x * 8 + threadIdx.x] = 0;

    int warp = threadIdx.x >> 5, lane = threadIdx.x & 31;
    int row = (blockIdx.x << 3) + warp;
    const float4* yr = (const float4*)Y + (size_t)row * (CDIM / 4);
    float4 v0 = yr[lane];
    float4 v1 = yr[lane + 32];
    float ss = 0.f;
    ss = fmaf(v0.x, v0.x, ss); ss = fmaf(v0.y, v0.y, ss);
    ss = fmaf(v0.z, v0.z, ss); ss = fmaf(v0.w, v0.w, ss);
    ss = fmaf(v1.x, v1.x, ss); ss = fmaf(v1.y, v1.y, ss);
    ss = fmaf(v1.z, v1.z, ss); ss = fmaf(v1.w, v1.w, ss);
    #pragma unroll
    for (int off = 16; off; off >>= 1)
        ss += __shfl_xor_sync(0xffffffffu, ss, off);
    if (lane == 0) g_b[row] = -ss;
}

// ---------------------------------------------------------------------------
// GEMM: M = 2 * X * Y^T, plus transposed copy MT.
// ---------------------------------------------------------------------------
__global__ __launch_bounds__(256) void gemm_kernel(const float* __restrict__ X,
                                                   const float* __restrict__ Y)
{
    __shared__ float As[16][128];
    __shared__ float Bs[16][128];

    const int tid = threadIdx.x;
    const int tx = tid & 15;
    const int ty = tid >> 4;
    const int i0 = blockIdx.y << 7;
    const int j0 = blockIdx.x << 7;

    const float4* X4 = (const float4*)X;
    const float4* Y4 = (const float4*)Y;

    float acc[8][8];
    #pragma unroll
    for (int r = 0; r < 8; r++)
        #pragma unroll
        for (int c = 0; c < 8; c++) acc[r][c] = 0.f;

    for (int k0 = 0; k0 < CDIM; k0 += 16) {
        #pragma unroll
        for (int p = 0; p < 2; p++) {
            int f = tid + (p << 8);
            int r = f >> 2;
            int q = f & 3;
            float4 a = X4[(size_t)(i0 + r) * (CDIM / 4) + (k0 >> 2) + q];
            As[q * 4 + 0][r] = a.x; As[q * 4 + 1][r] = a.y;
            As[q * 4 + 2][r] = a.z; As[q * 4 + 3][r] = a.w;
            float4 b = Y4[(size_t)(j0 + r) * (CDIM / 4) + (k0 >> 2) + q];
            Bs[q * 4 + 0][r] = b.x; Bs[q * 4 + 1][r] = b.y;
            Bs[q * 4 + 2][r] = b.z; Bs[q * 4 + 3][r] = b.w;
        }
        __syncthreads();
        #pragma unroll
        for (int kk = 0; kk < 16; kk++) {
            float af[8], bf[8];
            *(float4*)&af[0] = *(const float4*)&As[kk][ty * 8];
            *(float4*)&af[4] = *(const float4*)&As[kk][ty * 8 + 4];
            *(float4*)&bf[0] = *(const float4*)&Bs[kk][tx * 8];
            *(float4*)&bf[4] = *(const float4*)&Bs[kk][tx * 8 + 4];
            #pragma unroll
            for (int r = 0; r < 8; r++)
                #pragma unroll
                for (int c = 0; c < 8; c++)
                    acc[r][c] = fmaf(af[r], bf[c], acc[r][c]);
        }
        __syncthreads();
    }

    #pragma unroll
    for (int r = 0; r < 8; r++) {
        int i = i0 + ty * 8 + r;
        float4 w0 = make_float4(2.f * acc[r][0], 2.f * acc[r][1],
                                2.f * acc[r][2], 2.f * acc[r][3]);
        float4 w1 = make_float4(2.f * acc[r][4], 2.f * acc[r][5],
                                2.f * acc[r][6], 2.f * acc[r][7]);
        float4* dst = (float4*)(g_M + (size_t)i * BDIM + j0 + tx * 8);
        dst[0] = w0; dst[1] = w1;
    }
    #pragma unroll
    for (int c = 0; c < 8; c++) {
        int j = j0 + tx * 8 + c;
        float4 t0 = make_float4(2.f * acc[0][c], 2.f * acc[1][c],
                                2.f * acc[2][c], 2.f * acc[3][c]);
        float4 t1 = make_float4(2.f * acc[4][c], 2.f * acc[5][c],
                                2.f * acc[6][c], 2.f * acc[7][c]);
        float4* dst = (float4*)(g_MT + (size_t)j * BDIM + i0 + ty * 8);
        dst[0] = t0; dst[1] = t1;
    }
}

// ---------------------------------------------------------------------------
// Dense LSE pass with chip-wide work-stealing:
//   dst[row] = -logsumexp_j( Mmat[row][j] + src[j] )
// Work unit = 1024-col chunk; warps pull tickets from g_tickets[pass_id].
// Each chunk's exact (max,sum) goes to fixed slot g_pp[chunk]; the warp
// whose arrival makes the row complete combines the 8 pairs in fixed slot
// order (bitwise deterministic) and resets the row counter for next pass.
// ---------------------------------------------------------------------------
__global__ __launch_bounds__(512, 2) void lse_pass_kernel(const float* __restrict__ Mmat,
                                                          const float* __restrict__ src,
                                                          float* __restrict__ dst,
                                                          int pass_id)
{
    __shared__ float sb[BDIM];
    const int tid = threadIdx.x;
    const int lane = tid & 31;

    // stage src
    float4* sb4 = (float4*)sb;
    const float4* s4 = (const float4*)src;
    #pragma unroll
    for (int k = 0; k < 4; k++) sb4[tid + 512 * k] = s4[tid + 512 * k];
    __syncthreads();

    int* ticket = &g_tickets[pass_id];

    for (;;) {
        int t;
        if (lane == 0) t = atomicAdd(ticket, 1);
        t = __shfl_sync(0xffffffffu, t, 0);
        if (t >= NCHUNK) break;

        const int r  = t >> 3;
        const int cb = (t & 7) << 8;                  // chunk base, float4 units
        const float4* m4 = (const float4*)(Mmat + ((size_t)r << 13)) + cb + lane;
        const float4* b4 = sb4 + cb + lane;

        float4 v[8];
        #pragma unroll
        for (int u = 0; u < 8; u++) {
            float4 mm = __ldcs(m4 + 32 * u);
            float4 bb = b4[32 * u];
            v[u].x = mm.x + bb.x; v[u].y = mm.y + bb.y;
            v[u].z = mm.z + bb.z; v[u].w = mm.w + bb.w;
        }
        float tt[8];
        #pragma unroll
        for (int u = 0; u < 8; u++)
            tt[u] = fmaxf(fmaxf(v[u].x, v[u].y), fmaxf(v[u].z, v[u].w));
        float lmax = fmaxf(fmaxf(fmaxf(tt[0], tt[1]), fmaxf(tt[2], tt[3])),
                           fmaxf(fmaxf(tt[4], tt[5]), fmaxf(tt[6], tt[7])));
        #pragma unroll
        for (int off = 16; off; off >>= 1)
            lmax = fmaxf(lmax, __shfl_xor_sync(0xffffffffu, lmax, off));

        const float mk = lmax * L2E;
        float s = 0.f;
        #pragma unroll
        for (int u = 0; u < 8; u++) {
            s += ex2f(fmaf(v[u].x, L2E, -mk));
            s += ex2f(fmaf(v[u].y, L2E, -mk));
            s += ex2f(fmaf(v[u].z, L2E, -mk));
            s += ex2f(fmaf(v[u].w, L2E, -mk));
        }
        #pragma unroll
        for (int off = 16; off; off >>= 1)
            s += __shfl_xor_sync(0xffffffffu, s, off);

        if (lane == 0) {
            g_pp[t] = make_float2(lmax, s);
            __threadfence();                          // publish before arrive
            int c = atomicAdd(&g_rowcnt[r], 1);
            if (c == 7) {                             // last chunk of this row
                __threadfence();                      // acquire all 8 slots
                const float2* pp = &g_pp[r * 8];
                float2 p[8];
                #pragma unroll
                for (int k = 0; k < 8; k++) p[k] = pp[k];
                float m = p[0].x;
                #pragma unroll
                for (int k = 1; k < 8; k++) m = fmaxf(m, p[k].x);
                float ss = 0.f;
                #pragma unroll
                for (int k = 0; k < 8; k++)
                    ss += p[k].y * ex2f((p[k].x - m) * L2E);
                dst[r] = -(m + lg2f(ss) * LN2);
                g_rowcnt[r] = 0;                      // self-reset for next pass
            }
        }
    }
}

// ---------------------------------------------------------------------------
// Final: out[i][:] = y[ argmax_j (M[i][j] + b[j]) ][:]   (full scan, runs once)
// ---------------------------------------------------------------------------
__global__ __launch_bounds__(256) void argmax_gather_kernel(const float* __restrict__ Y,
                                                            float* __restrict__ out)
{
    __shared__ float sb[BDIM];
    __shared__ float sval[8];
    __shared__ int   sidx[8];
    __shared__ int   sjbest;
    const int tid = threadIdx.x;
    const int lane = tid & 31, warp = tid >> 5;

    float4* sb4 = (float4*)sb;
    const float4* s4 = (const float4*)g_b;
    #pragma unroll
    for (int k = 0; k < 8; k++) sb4[tid + 256 * k] = s4[tid + 256 * k];
    __syncthreads();

    const int row0 = blockIdx.x << 3;
    for (int rr = 0; rr < 8; rr++) {
        const int row = row0 + rr;
        const float4* m4 = (const float4*)(g_M + (size_t)row * BDIM);

        float best = -3.0e38f;
        int bidx = 0x7fffffff;
        #pragma unroll
        for (int k = 0; k < 8; k++) {
            int f = tid + 256 * k;
            float4 m = __ldcs(m4 + f);
            float4 bb = sb4[f];
            float vx = m.x + bb.x, vy = m.y + bb.y, vz = m.z + bb.z, vw = m.w + bb.w;
            int j = f * 4;
            if (vx > best || (vx == best && j     < bidx)) { best = vx; bidx = j; }
            if (vy > best || (vy == best && j + 1 < bidx)) { best = vy; bidx = j + 1; }
            if (vz > best || (vz == best && j + 2 < bidx)) { best = vz; bidx = j + 2; }
            if (vw > best || (vw == best && j + 3 < bidx)) { best = vw; bidx = j + 3; }
        }
        #pragma unroll
        for (int off = 16; off; off >>= 1) {
            float ov = __shfl_xor_sync(0xffffffffu, best, off);
            int   oi = __shfl_xor_sync(0xffffffffu, bidx, off);
            if (ov > best || (ov == best && oi < bidx)) { best = ov; bidx = oi; }
        }
        if (lane == 0) { sval[warp] = best; sidx[warp] = bidx; }
        __syncthreads();
        if (tid == 0) {
            float bv = sval[0]; int bj = sidx[0];
            #pragma unroll
            for (int w = 1; w < 8; w++) {
                if (sval[w] > bv || (sval[w] == bv && sidx[w] < bj)) {
                    bv = sval[w]; bj = sidx[w];
                }
            }
            sjbest = bj;
        }
        __syncthreads();
        out[(size_t)row * CDIM + tid] = Y[(size_t)sjbest * CDIM + tid];
        __syncthreads();
    }
}

// ---------------------------------------------------------------------------
extern "C" void kernel_launch(void* const* d_in, const int* in_sizes, int n_in,
                              void* d_out, int out_size)
{
    const float* X = (const float*)d_in[0];
    const float* Y = (const float*)d_in[1];
    float* out = (float*)d_out;

    float *Mp, *MTp, *ap, *bp;
    cudaGetSymbolAddress((void**)&Mp,  g_M);
    cudaGetSymbolAddress((void**)&MTp, g_MT);
    cudaGetSymbolAddress((void**)&ap,  g_a);
    cudaGetSymbolAddress((void**)&bp,  g_b);

    int nsm = 148;
    cudaDeviceGetAttribute(&nsm, cudaDevAttrMultiProcessorCount, 0);
    int grid = 2 * nsm;

    init_b_kernel<<<BDIM / 8, 256>>>(Y);

    dim3 ggrid(BDIM / 128, BDIM / 128);
    gemm_kernel<<<ggrid, 256>>>(X, Y);

    for (int it = 0; it < NITER; it++) {
        lse_pass_kernel<<<grid, 512>>>(Mp,  bp, ap, 2 * it);      // a = -lse_row(M + b)
        lse_pass_kernel<<<grid, 512>>>(MTp, ap, bp, 2 * it + 1);  // b = -lse_col(M + a)
    }

    argmax_gather_kernel<<<BDIM / 8, 256>>>(Y, out);
}

// round 10
// speedup vs baseline: 2.1755x; 2.1755x over previous
#include <cuda_runtime.h>
#include <cstdint>
#include <cstddef>

#define BDIM 8192
#define CDIM 256
#define NITER 100
#define MAXROWS 64
#define L2E 1.4426950408889634f
#define LN2 0.69314718055994531f

// Scratch: __device__ globals (no cudaMalloc allowed)
__device__ __align__(256) float g_M [(size_t)BDIM * BDIM];  // M[i][j]  = 2*x_i.y_j
__device__ __align__(256) float g_MT[(size_t)BDIM * BDIM];  // MT[j][i] = M[i][j]
__device__ __align__(256) float g_a[BDIM];
__device__ __align__(256) float g_b[BDIM];

__device__ __forceinline__ float ex2f(float x) {
    float y; asm("ex2.approx.f32 %0, %1;" : "=f"(y) : "f"(x)); return y;
}
__device__ __forceinline__ float lg2f(float x) {
    float y; asm("lg2.approx.f32 %0, %1;" : "=f"(y) : "f"(x)); return y;
}

// ---------------------------------------------------------------------------
// b init: b[j] = -||y_j||^2   (one warp per row, 8 rows per block)
// ---------------------------------------------------------------------------
__global__ __launch_bounds__(256) void init_b_kernel(const float* __restrict__ Y)
{
    int warp = threadIdx.x >> 5, lane = threadIdx.x & 31;
    int row = (blockIdx.x << 3) + warp;
    const float4* yr = (const float4*)Y + (size_t)row * (CDIM / 4);
    float4 v0 = yr[lane];
    float4 v1 = yr[lane + 32];
    float ss = 0.f;
    ss = fmaf(v0.x, v0.x, ss); ss = fmaf(v0.y, v0.y, ss);
    ss = fmaf(v0.z, v0.z, ss); ss = fmaf(v0.w, v0.w, ss);
    ss = fmaf(v1.x, v1.x, ss); ss = fmaf(v1.y, v1.y, ss);
    ss = fmaf(v1.z, v1.z, ss); ss = fmaf(v1.w, v1.w, ss);
    #pragma unroll
    for (int off = 16; off; off >>= 1)
        ss += __shfl_xor_sync(0xffffffffu, ss, off);
    if (lane == 0) g_b[row] = -ss;
}

// ---------------------------------------------------------------------------
// GEMM: M = 2 * X * Y^T, plus transposed copy MT.
// 128x128 tile, 256 threads, 8x8 per thread, k-step 16.
// Inner product uses packed fma.rn.f32x2 (FFMA2): two fp32 FMAs per
// instruction, bitwise identical to scalar FFMA, halves fma-pipe issue.
// ---------------------------------------------------------------------------
__global__ __launch_bounds__(256) void gemm_kernel(const float* __restrict__ X,
                                                   const float* __restrict__ Y)
{
    __shared__ float As[16][128];
    __shared__ float Bs[16][128];

    const int tid = threadIdx.x;
    const int tx = tid & 15;
    const int ty = tid >> 4;
    const int i0 = blockIdx.y << 7;
    const int j0 = blockIdx.x << 7;

    const float4* X4 = (const float4*)X;
    const float4* Y4 = (const float4*)Y;

    // acc2[r][c2] holds columns {2*c2, 2*c2+1} packed (low = even col)
    unsigned long long acc2[8][4];
    #pragma unroll
    for (int r = 0; r < 8; r++)
        #pragma unroll
        for (int c = 0; c < 4; c++) acc2[r][c] = 0ull;

    for (int k0 = 0; k0 < CDIM; k0 += 16) {
        #pragma unroll
        for (int p = 0; p < 2; p++) {
            int f = tid + (p << 8);          // 0..511
            int r = f >> 2;                  // tile row 0..127
            int q = f & 3;                   // k-quad 0..3
            float4 a = X4[(size_t)(i0 + r) * (CDIM / 4) + (k0 >> 2) + q];
            As[q * 4 + 0][r] = a.x; As[q * 4 + 1][r] = a.y;
            As[q * 4 + 2][r] = a.z; As[q * 4 + 3][r] = a.w;
            float4 b = Y4[(size_t)(j0 + r) * (CDIM / 4) + (k0 >> 2) + q];
            Bs[q * 4 + 0][r] = b.x; Bs[q * 4 + 1][r] = b.y;
            Bs[q * 4 + 2][r] = b.z; Bs[q * 4 + 3][r] = b.w;
        }
        __syncthreads();
        #pragma unroll
        for (int kk = 0; kk < 16; kk++) {
            float af[8];
            *(float4*)&af[0] = *(const float4*)&As[kk][ty * 8];
            *(float4*)&af[4] = *(const float4*)&As[kk][ty * 8 + 4];
            unsigned long long bf2[4];
            const unsigned long long* bsp =
                (const unsigned long long*)&Bs[kk][tx * 8];
            bf2[0] = bsp[0]; bf2[1] = bsp[1]; bf2[2] = bsp[2]; bf2[3] = bsp[3];
            #pragma unroll
            for (int r = 0; r < 8; r++) {
                unsigned long long a2;
                asm("mov.b64 %0, {%1, %1};" : "=l"(a2) : "f"(af[r]));
                #pragma unroll
                for (int c = 0; c < 4; c++)
                    asm("fma.rn.f32x2 %0, %1, %2, %0;"
                        : "+l"(acc2[r][c]) : "l"(a2), "l"(bf2[c]));
            }
        }
        __syncthreads();
    }

    // unpack accumulators (low 32 bits = even column)
    float acc[8][8];
    #pragma unroll
    for (int r = 0; r < 8; r++)
        #pragma unroll
        for (int c = 0; c < 4; c++) {
            acc[r][2 * c]     = __uint_as_float((unsigned int)acc2[r][c]);
            acc[r][2 * c + 1] = __uint_as_float((unsigned int)(acc2[r][c] >> 32));
        }

    // M tile (coalesced rows)
    #pragma unroll
    for (int r = 0; r < 8; r++) {
        int i = i0 + ty * 8 + r;
        float4 w0 = make_float4(2.f * acc[r][0], 2.f * acc[r][1],
                                2.f * acc[r][2], 2.f * acc[r][3]);
        float4 w1 = make_float4(2.f * acc[r][4], 2.f * acc[r][5],
                                2.f * acc[r][6], 2.f * acc[r][7]);
        float4* dst = (float4*)(g_M + (size_t)i * BDIM + j0 + tx * 8);
        dst[0] = w0; dst[1] = w1;
    }
    // MT tile
    #pragma unroll
    for (int c = 0; c < 8; c++) {
        int j = j0 + tx * 8 + c;
        float4 t0 = make_float4(2.f * acc[0][c], 2.f * acc[1][c],
                                2.f * acc[2][c], 2.f * acc[3][c]);
        float4 t1 = make_float4(2.f * acc[4][c], 2.f * acc[5][c],
                                2.f * acc[6][c], 2.f * acc[7][c]);
        float4* dst = (float4*)(g_MT + (size_t)j * BDIM + i0 + ty * 8);
        dst[0] = t0; dst[1] = t1;
    }
}

// ---------------------------------------------------------------------------
// Dense LSE pass, single-wave balanced (R6 champion, unchanged):
//   dst[row] = -logsumexp_j( Mmat[row][j] + src[j] )
// ---------------------------------------------------------------------------
__global__ __launch_bounds__(512, 2) void lse_pass_kernel(const float* __restrict__ Mmat,
                                                          const float* __restrict__ src,
                                                          float* __restrict__ dst)
{
    __shared__ float sb[BDIM];
    __shared__ float pm[MAXROWS * 8];
    __shared__ float ps[MAXROWS * 8];

    const int tid  = threadIdx.x;
    const int lane = tid & 31, warp = tid >> 5;
    const int nw   = blockDim.x >> 5;
    const int nblk = gridDim.x;
    const int r0   = (int)(((long long)BDIM * blockIdx.x) / nblk);
    const int r1   = (int)(((long long)BDIM * (blockIdx.x + 1)) / nblk);
    const int nrows = r1 - r0;
    const int nch   = nrows << 3;

    float4* sb4 = (float4*)sb;
    const float4* s4 = (const float4*)src;
    #pragma unroll
    for (int k = 0; k < 4; k++) sb4[tid + 512 * k] = s4[tid + 512 * k];
    __syncthreads();

    for (int c = warp; c < nch; c += nw) {
        const int r = c >> 3;
        const int cb = (c & 7) << 8;
        const float4* m4 = (const float4*)(Mmat + ((size_t)(r0 + r) << 13)) + cb + lane;
        const float4* b4 = sb4 + cb + lane;

        float4 v[8];
        #pragma unroll
        for (int u = 0; u < 8; u++) {
            float4 mm = __ldcs(m4 + 32 * u);
            float4 bb = b4[32 * u];
            v[u].x = mm.x + bb.x; v[u].y = mm.y + bb.y;
            v[u].z = mm.z + bb.z; v[u].w = mm.w + bb.w;
        }
        float t[8];
        #pragma unroll
        for (int u = 0; u < 8; u++)
            t[u] = fmaxf(fmaxf(v[u].x, v[u].y), fmaxf(v[u].z, v[u].w));
        float lmax = fmaxf(fmaxf(fmaxf(t[0], t[1]), fmaxf(t[2], t[3])),
                           fmaxf(fmaxf(t[4], t[5]), fmaxf(t[6], t[7])));
        #pragma unroll
        for (int off = 16; off; off >>= 1)
            lmax = fmaxf(lmax, __shfl_xor_sync(0xffffffffu, lmax, off));

        const float mk = lmax * L2E;
        float s = 0.f;
        #pragma unroll
        for (int u = 0; u < 8; u++) {
            s += ex2f(fmaf(v[u].x, L2E, -mk));
            s += ex2f(fmaf(v[u].y, L2E, -mk));
            s += ex2f(fmaf(v[u].z, L2E, -mk));
            s += ex2f(fmaf(v[u].w, L2E, -mk));
        }
        #pragma unroll
        for (int off = 16; off; off >>= 1)
            s += __shfl_xor_sync(0xffffffffu, s, off);

        if (lane == 0) { pm[c] = lmax; ps[c] = s; }
    }
    __syncthreads();

    for (int r = tid; r < nrows; r += blockDim.x) {
        float m = pm[r * 8];
        #pragma unroll
        for (int k = 1; k < 8; k++) m = fmaxf(m, pm[r * 8 + k]);
        float s = 0.f;
        #pragma unroll
        for (int k = 0; k < 8; k++)
            s += ps[r * 8 + k] * ex2f((pm[r * 8 + k] - m) * L2E);
        dst[r0 + r] = -(m + lg2f(s) * LN2);
    }
}

// ---------------------------------------------------------------------------
// Final: out[i][:] = y[ argmax_j (M[i][j] + b[j]) ][:]
// ---------------------------------------------------------------------------
__global__ __launch_bounds__(256) void argmax_gather_kernel(const float* __restrict__ Y,
                                                            float* __restrict__ out)
{
    __shared__ float sb[BDIM];
    __shared__ float sval[8];
    __shared__ int   sidx[8];
    __shared__ int   sjbest;
    const int tid = threadIdx.x;
    const int lane = tid & 31, warp = tid >> 5;

    float4* sb4 = (float4*)sb;
    const float4* s4 = (const float4*)g_b;
    #pragma unroll
    for (int k = 0; k < 8; k++) sb4[tid + 256 * k] = s4[tid + 256 * k];
    __syncthreads();

    const int row0 = blockIdx.x << 3;
    for (int rr = 0; rr < 8; rr++) {
        const int row = row0 + rr;
        const float4* m4 = (const float4*)(g_M + (size_t)row * BDIM);

        float best = -3.0e38f;
        int bidx = 0x7fffffff;
        #pragma unroll
        for (int k = 0; k < 8; k++) {
            int f = tid + 256 * k;
            float4 m = __ldcs(m4 + f);
            float4 bb = sb4[f];
            float vx = m.x + bb.x, vy = m.y + bb.y, vz = m.z + bb.z, vw = m.w + bb.w;
            int j = f * 4;
            if (vx > best || (vx == best && j     < bidx)) { best = vx; bidx = j; }
            if (vy > best || (vy == best && j + 1 < bidx)) { best = vy; bidx = j + 1; }
            if (vz > best || (vz == best && j + 2 < bidx)) { best = vz; bidx = j + 2; }
            if (vw > best || (vw == best && j + 3 < bidx)) { best = vw; bidx = j + 3; }
        }
        #pragma unroll
        for (int off = 16; off; off >>= 1) {
            float ov = __shfl_xor_sync(0xffffffffu, best, off);
            int   oi = __shfl_xor_sync(0xffffffffu, bidx, off);
            if (ov > best || (ov == best && oi < bidx)) { best = ov; bidx = oi; }
        }
        if (lane == 0) { sval[warp] = best; sidx[warp] = bidx; }
        __syncthreads();
        if (tid == 0) {
            float bv = sval[0]; int bj = sidx[0];
            #pragma unroll
            for (int w = 1; w < 8; w++) {
                if (sval[w] > bv || (sval[w] == bv && sidx[w] < bj)) {
                    bv = sval[w]; bj = sidx[w];
                }
            }
            sjbest = bj;
        }
        __syncthreads();
        out[(size_t)row * CDIM + tid] = Y[(size_t)sjbest * CDIM + tid];
        __syncthreads();
    }
}

// ---------------------------------------------------------------------------
extern "C" void kernel_launch(void* const* d_in, const int* in_sizes, int n_in,
                              void* d_out, int out_size)
{
    const float* X = (const float*)d_in[0];
    const float* Y = (const float*)d_in[1];
    float* out = (float*)d_out;

    float *Mp, *MTp, *ap, *bp;
    cudaGetSymbolAddress((void**)&Mp,  g_M);
    cudaGetSymbolAddress((void**)&MTp, g_MT);
    cudaGetSymbolAddress((void**)&ap,  g_a);
    cudaGetSymbolAddress((void**)&bp,  g_b);

    int nsm = 148;
    cudaDeviceGetAttribute(&nsm, cudaDevAttrMultiProcessorCount, 0);
    int grid = 2 * nsm;
    if (grid < BDIM / MAXROWS) grid = BDIM / MAXROWS;

    init_b_kernel<<<BDIM / 8, 256>>>(Y);

    dim3 ggrid(BDIM / 128, BDIM / 128);
    gemm_kernel<<<ggrid, 256>>>(X, Y);

    for (int it = 0; it < NITER; it++) {
        lse_pass_kernel<<<grid, 512>>>(Mp,  bp, ap);   // a = -lse_row(M + b)
        lse_pass_kernel<<<grid, 512>>>(MTp, ap, bp);   // b = -lse_col(M + a)
    }

    argmax_gather_kernel<<<BDIM / 8, 256>>>(Y, out);
}